// round 3
// baseline (speedup 1.0000x reference)
#include <cuda_runtime.h>

// GCN: h1 = relu(GCNConv(x, W1, b1)); h2 = GCNConv(h1, W2, b2);
// g = segment_sum(h2, batch); out = log_softmax(g @ Wlin + blin)
//
// Formulation: out[c] = dinv[c] * ( sum_{e: col(e)=c} hs[row(e)] + hs[c] ) + b
// with hs = (x @ W) * dinv  (pre-scaled by source dinv; self-loop folds in).
//
// Index dtype (int32 vs int64) is detected at runtime on-device and converted
// into int32 scratch, so both harness conventions work.

static const int NN = 100000;
static const int NG = 1024;
static const int EMAX = 3200000;

// Scratch (device globals; no allocation allowed)
__device__ int    g_is64;
__device__ int    g_idx32[2 * EMAX];   // [0,E): rows, [E,2E): cols
__device__ int    g_batch32[NN];
__device__ __align__(16) float g_dinv[NN];
__device__ float4 g_hs1[NN * 4];
__device__ float4 g_t1 [NN * 4];
__device__ float4 g_hs2[NN * 4];
__device__ float4 g_t2 [NN * 4];
__device__ float4 g_pool[NG * 4];

__device__ __forceinline__ void red_add_v4(float* addr, float4 v) {
    asm volatile("red.global.add.v4.f32 [%0], {%1, %2, %3, %4};"
                 :: "l"(addr), "f"(v.x), "f"(v.y), "f"(v.z), "f"(v.w)
                 : "memory");
}

// ---------------------------------------------------------------------------
// 0a) dtype detect: int64 indices < 2^31 have all-zero high words; int32 data
//     interpreted as int64 has random nonzero high words.
__global__ void k_detect(const void* __restrict__ ei, int twoE) {
    __shared__ int bad;
    if (threadIdx.x == 0) bad = 0;
    __syncthreads();
    const long long* p64 = (const long long*)ei;
    int n = twoE / 2 < 2048 ? twoE / 2 : 2048;  // sample int64-view entries
    for (int i = threadIdx.x; i < n; i += blockDim.x) {
        unsigned long long v = (unsigned long long)p64[i];
        if (v >> 32) bad = 1;   // benign race
    }
    __syncthreads();
    if (threadIdx.x == 0) g_is64 = bad ? 0 : 1;
}

// 0b) convert edge indices to int32 scratch
__global__ void k_conv_edges(const void* __restrict__ ei, int twoE) {
    int i = blockIdx.x * blockDim.x + threadIdx.x;
    if (i >= twoE) return;
    if (g_is64) g_idx32[i] = (int)((const long long*)ei)[i];
    else        g_idx32[i] = ((const int*)ei)[i];
}

// 0c) convert batch to int32 scratch
__global__ void k_conv_batch(const void* __restrict__ b) {
    int i = blockIdx.x * blockDim.x + threadIdx.x;
    if (i >= NN) return;
    if (g_is64) g_batch32[i] = (int)((const long long*)b)[i];
    else        g_batch32[i] = ((const int*)b)[i];
}

// 1) init: zero accumulators, deg starts at 1.0 (self loop)
__global__ void k_init() {
    int i = blockIdx.x * blockDim.x + threadIdx.x;
    float4 z = make_float4(0.f, 0.f, 0.f, 0.f);
    if (i < NN * 4) { g_t1[i] = z; g_t2[i] = z; }
    if (i < NN)       g_dinv[i] = 1.0f;
    if (i < NG * 4)   g_pool[i] = z;
}

// 2) degree over targets (incl. self loop via init=1)
__global__ void k_deg(int E) {
    int e = blockIdx.x * blockDim.x + threadIdx.x;
    if (e < E) {
        int c = g_idx32[E + e];
        atomicAdd(&g_dinv[c], 1.0f);
    }
}

// 3) dinv = rsqrt(deg) in place
__global__ void k_rsqrt() {
    int i = blockIdx.x * blockDim.x + threadIdx.x;
    if (i < NN) g_dinv[i] = rsqrtf(g_dinv[i]);
}

// 4) hs1 = (x @ W1) * dinv    (x: [N,3], W1: [3,16])
__global__ void k_hs1(const float* __restrict__ x, const float* __restrict__ W1) {
    __shared__ float sW[48];
    if (threadIdx.x < 48) sW[threadIdx.x] = W1[threadIdx.x];
    __syncthreads();
    int i = blockIdx.x * blockDim.x + threadIdx.x;
    if (i >= NN) return;
    float x0 = __ldg(x + 3 * i + 0);
    float x1 = __ldg(x + 3 * i + 1);
    float x2 = __ldg(x + 3 * i + 2);
    float di = g_dinv[i];
    float h[16];
#pragma unroll
    for (int j = 0; j < 16; j++)
        h[j] = di * (x0 * sW[j] + x1 * sW[16 + j] + x2 * sW[32 + j]);
    float4* dst = &g_hs1[i * 4];
    dst[0] = make_float4(h[0],  h[1],  h[2],  h[3]);
    dst[1] = make_float4(h[4],  h[5],  h[6],  h[7]);
    dst[2] = make_float4(h[8],  h[9],  h[10], h[11]);
    dst[3] = make_float4(h[12], h[13], h[14], h[15]);
}

// 5) edge scatter: t[col] += hs[row]
template <int LAYER>
__global__ void k_scatter(int E) {
    int e = blockIdx.x * blockDim.x + threadIdx.x;
    if (e >= E) return;
    int r = g_idx32[e];
    int c = g_idx32[E + e];
    const float4* hs = (LAYER == 0) ? g_hs1 : g_hs2;
    float4*       t  = (LAYER == 0) ? g_t1  : g_t2;
    float4 a  = __ldg(hs + r * 4 + 0);
    float4 b  = __ldg(hs + r * 4 + 1);
    float4 cc = __ldg(hs + r * 4 + 2);
    float4 d  = __ldg(hs + r * 4 + 3);
    float* dst = (float*)(t + c * 4);
    red_add_v4(dst + 0,  a);
    red_add_v4(dst + 4,  b);
    red_add_v4(dst + 8,  cc);
    red_add_v4(dst + 12, d);
}

// 6) layer-1 epilogue + layer-2 linear: v = relu(dinv*(t1+hs1)+b1); hs2 = (v@W2)*dinv
__global__ void k_mid(const float* __restrict__ b1, const float* __restrict__ W2) {
    __shared__ float sW[256];
    __shared__ float sb[16];
    if (threadIdx.x < 256) sW[threadIdx.x] = W2[threadIdx.x];
    if (threadIdx.x < 16)  sb[threadIdx.x] = b1[threadIdx.x];
    __syncthreads();
    int i = blockIdx.x * blockDim.x + threadIdx.x;
    if (i >= NN) return;
    float di = g_dinv[i];
    float v[16];
#pragma unroll
    for (int q = 0; q < 4; q++) {
        float4 t = g_t1[i * 4 + q];
        float4 h = g_hs1[i * 4 + q];
        v[q * 4 + 0] = fmaxf(fmaf(di, t.x + h.x, sb[q * 4 + 0]), 0.f);
        v[q * 4 + 1] = fmaxf(fmaf(di, t.y + h.y, sb[q * 4 + 1]), 0.f);
        v[q * 4 + 2] = fmaxf(fmaf(di, t.z + h.z, sb[q * 4 + 2]), 0.f);
        v[q * 4 + 3] = fmaxf(fmaf(di, t.w + h.w, sb[q * 4 + 3]), 0.f);
    }
    float o[16];
#pragma unroll
    for (int j = 0; j < 16; j++) {
        float acc = 0.f;
#pragma unroll
        for (int k = 0; k < 16; k++)
            acc = fmaf(v[k], sW[k * 16 + j], acc);
        o[j] = di * acc;
    }
    float4* dst = &g_hs2[i * 4];
    dst[0] = make_float4(o[0],  o[1],  o[2],  o[3]);
    dst[1] = make_float4(o[4],  o[5],  o[6],  o[7]);
    dst[2] = make_float4(o[8],  o[9],  o[10], o[11]);
    dst[3] = make_float4(o[12], o[13], o[14], o[15]);
}

// 7) layer-2 epilogue + pool: h2 = dinv*(t2+hs2)+b2; pool[batch[i]] += h2
__global__ void k_final(const float* __restrict__ b2) {
    __shared__ float sb[16];
    if (threadIdx.x < 16) sb[threadIdx.x] = b2[threadIdx.x];
    __syncthreads();
    int i = blockIdx.x * blockDim.x + threadIdx.x;
    if (i >= NN) return;
    float di = g_dinv[i];
    int g = g_batch32[i];
    float* dst = (float*)&g_pool[g * 4];
#pragma unroll
    for (int q = 0; q < 4; q++) {
        float4 t = g_t2[i * 4 + q];
        float4 h = g_hs2[i * 4 + q];
        float4 r;
        r.x = fmaf(di, t.x + h.x, sb[q * 4 + 0]);
        r.y = fmaf(di, t.y + h.y, sb[q * 4 + 1]);
        r.z = fmaf(di, t.z + h.z, sb[q * 4 + 2]);
        r.w = fmaf(di, t.w + h.w, sb[q * 4 + 3]);
        red_add_v4(dst + q * 4, r);
    }
}

// 8) per-graph head: logits = pool @ Wlin + blin; log_softmax
__global__ void k_logits(const float* __restrict__ Wlin, const float* __restrict__ blin,
                         float* __restrict__ out) {
    int g = blockIdx.x * blockDim.x + threadIdx.x;
    if (g >= NG) return;
    float gv[16];
#pragma unroll
    for (int q = 0; q < 4; q++) {
        float4 p = g_pool[g * 4 + q];
        gv[q * 4 + 0] = p.x; gv[q * 4 + 1] = p.y;
        gv[q * 4 + 2] = p.z; gv[q * 4 + 3] = p.w;
    }
    float lg[7];
#pragma unroll
    for (int o = 0; o < 7; o++) {
        float acc = __ldg(blin + o);
#pragma unroll
        for (int k = 0; k < 16; k++)
            acc = fmaf(gv[k], __ldg(Wlin + k * 7 + o), acc);
        lg[o] = acc;
    }
    float m = lg[0];
#pragma unroll
    for (int o = 1; o < 7; o++) m = fmaxf(m, lg[o]);
    float s = 0.f;
#pragma unroll
    for (int o = 0; o < 7; o++) s += expf(lg[o] - m);
    float ls = logf(s) + m;
#pragma unroll
    for (int o = 0; o < 7; o++) out[g * 7 + o] = lg[o] - ls;
}

// ---------------------------------------------------------------------------
extern "C" void kernel_launch(void* const* d_in, const int* in_sizes, int n_in,
                              void* d_out, int out_size) {
    int p = 0;
    const float* x     = (const float*)d_in[p]; p++;
    const void*  ei    = d_in[p];
    int twoE = in_sizes[p];
    int E = twoE / 2; p++;
    const void*  batch = d_in[p]; p++;
    if (p < n_in && in_sizes[p] == 1) p++;  // skip scalar num_graphs if present
    const float* W1   = (const float*)d_in[p]; p++;
    const float* b1   = (const float*)d_in[p]; p++;
    const float* W2   = (const float*)d_in[p]; p++;
    const float* b2   = (const float*)d_in[p]; p++;
    const float* Wlin = (const float*)d_in[p]; p++;
    const float* blin = (const float*)d_in[p]; p++;
    float* out = (float*)d_out;

    const int TB = 256;
    int gN  = (NN + TB - 1) / TB;
    int gN4 = (NN * 4 + TB - 1) / TB;
    int gE  = (E + TB - 1) / TB;
    int g2E = (twoE + TB - 1) / TB;

    k_detect    <<<1,   TB>>>(ei, twoE);
    k_conv_edges<<<g2E, TB>>>(ei, twoE);
    k_conv_batch<<<gN,  TB>>>(batch);
    k_init      <<<gN4, TB>>>();
    k_deg       <<<gE,  TB>>>(E);
    k_rsqrt     <<<gN,  TB>>>();
    k_hs1       <<<gN,  TB>>>(x, W1);
    k_scatter<0><<<gE,  TB>>>(E);
    k_mid       <<<gN,  TB>>>(b1, W2);
    k_scatter<1><<<gE,  TB>>>(E);
    k_final     <<<gN,  TB>>>(b2);
    k_logits    <<<(NG + TB - 1) / TB, TB>>>(Wlin, blin, out);
}

// round 4
// speedup vs baseline: 1.1496x; 1.1496x over previous
#include <cuda_runtime.h>

// GCN: h1 = relu(GCNConv(x, W1, b1)); h2 = GCNConv(h1, W2, b2);
// g = segment_sum(h2, batch); out = log_softmax(g @ Wlin + blin)
//
// out[c] = dinv[c] * ( sum_{e: col=c} hs[row] + hs[c] ) + b,  hs = (x@W)*dinv.
// This round: scatter+atomics replaced by on-device CSR build + register gather.

static const int NN = 100000;
static const int NG = 1024;
static const int EMAX = 3200000;
static const int NBLK = (NN + 255) / 256;   // 391 scan blocks

// Scratch (device globals; no allocation allowed)
__device__ int    g_is64;
__device__ int    g_idx32[2 * EMAX];   // [0,E): rows, [E,2E): cols
__device__ int    g_batch32[NN];
__device__ int    g_degi[NN];
__device__ int    g_start[NN + 1];
__device__ int    g_cursor[NN];
__device__ int    g_bsum[NBLK];
__device__ int    g_boff[NBLK];
__device__ int    g_srcs[EMAX];
__device__ __align__(16) float g_dinv[NN];
__device__ float4 g_hs1[NN * 4];
__device__ float4 g_hs2[NN * 4];
__device__ float4 g_pool[NG * 4];

__device__ __forceinline__ void red_add_v4(float* addr, float4 v) {
    asm volatile("red.global.add.v4.f32 [%0], {%1, %2, %3, %4};"
                 :: "l"(addr), "f"(v.x), "f"(v.y), "f"(v.z), "f"(v.w)
                 : "memory");
}

// ---------------------------------------------------------------------------
// 0a) dtype detect: int64 indices < 2^31 have all-zero high words.
__global__ void k_detect(const void* __restrict__ ei, int twoE) {
    __shared__ int bad;
    if (threadIdx.x == 0) bad = 0;
    __syncthreads();
    const long long* p64 = (const long long*)ei;
    int n = twoE / 2 < 2048 ? twoE / 2 : 2048;
    for (int i = threadIdx.x; i < n; i += blockDim.x) {
        unsigned long long v = (unsigned long long)p64[i];
        if (v >> 32) bad = 1;   // benign race
    }
    __syncthreads();
    if (threadIdx.x == 0) g_is64 = bad ? 0 : 1;
}

// 1) init: zero deg counts + pool
__global__ void k_init() {
    int i = blockIdx.x * blockDim.x + threadIdx.x;
    if (i < NN) g_degi[i] = 0;
    if (i < NG * 4) g_pool[i] = make_float4(0.f, 0.f, 0.f, 0.f);
}

// 2) convert edge indices to int32 scratch; fused target-degree count
__global__ void k_conv_edges(const void* __restrict__ ei, int twoE) {
    int i = blockIdx.x * blockDim.x + threadIdx.x;
    if (i >= twoE) return;
    int v;
    if (g_is64) v = (int)((const long long*)ei)[i];
    else        v = ((const int*)ei)[i];
    g_idx32[i] = v;
    if (i >= twoE / 2) atomicAdd(&g_degi[v], 1);   // cols half
}

__global__ void k_conv_batch(const void* __restrict__ b) {
    int i = blockIdx.x * blockDim.x + threadIdx.x;
    if (i >= NN) return;
    if (g_is64) g_batch32[i] = (int)((const long long*)b)[i];
    else        g_batch32[i] = ((const int*)b)[i];
}

// 3) prefix scan of degrees -> CSR starts (3 kernels)
__global__ void k_scanA() {
    __shared__ int sh[256];
    int t = threadIdx.x;
    int i = blockIdx.x * 256 + t;
    sh[t] = (i < NN) ? g_degi[i] : 0;
    __syncthreads();
    for (int off = 128; off > 0; off >>= 1) {
        if (t < off) sh[t] += sh[t + off];
        __syncthreads();
    }
    if (t == 0) g_bsum[blockIdx.x] = sh[0];
}

__global__ void k_scanB() {
    if (threadIdx.x == 0) {
        int run = 0;
        for (int b = 0; b < NBLK; b++) { g_boff[b] = run; run += g_bsum[b]; }
        g_start[NN] = run;   // == E
    }
}

__global__ void k_scanC() {
    __shared__ int sh[256];
    int t = threadIdx.x;
    int i = blockIdx.x * 256 + t;
    int v = (i < NN) ? g_degi[i] : 0;
    sh[t] = v;
    __syncthreads();
    // Hillis-Steele inclusive scan
    for (int off = 1; off < 256; off <<= 1) {
        int add = (t >= off) ? sh[t - off] : 0;
        __syncthreads();
        sh[t] += add;
        __syncthreads();
    }
    if (i < NN) {
        int excl = g_boff[blockIdx.x] + sh[t] - v;
        g_start[i]  = excl;
        g_cursor[i] = excl;
        g_dinv[i]   = rsqrtf((float)(v + 1));   // +1 self loop
    }
}

// 4) bucket edge sources by target -> g_srcs
__global__ void k_bucket(int E) {
    int e = blockIdx.x * blockDim.x + threadIdx.x;
    if (e >= E) return;
    int r = g_idx32[e];
    int c = g_idx32[E + e];
    int pos = atomicAdd(&g_cursor[c], 1);
    g_srcs[pos] = r;
}

// 5) hs1 = (x @ W1) * dinv    (x: [N,3], W1: [3,16])
__global__ void k_hs1(const float* __restrict__ x, const float* __restrict__ W1) {
    __shared__ float sW[48];
    if (threadIdx.x < 48) sW[threadIdx.x] = W1[threadIdx.x];
    __syncthreads();
    int i = blockIdx.x * blockDim.x + threadIdx.x;
    if (i >= NN) return;
    float x0 = __ldg(x + 3 * i + 0);
    float x1 = __ldg(x + 3 * i + 1);
    float x2 = __ldg(x + 3 * i + 2);
    float di = g_dinv[i];
    float h[16];
#pragma unroll
    for (int j = 0; j < 16; j++)
        h[j] = di * (x0 * sW[j] + x1 * sW[16 + j] + x2 * sW[32 + j]);
    float4* dst = &g_hs1[i * 4];
    dst[0] = make_float4(h[0],  h[1],  h[2],  h[3]);
    dst[1] = make_float4(h[4],  h[5],  h[6],  h[7]);
    dst[2] = make_float4(h[8],  h[9],  h[10], h[11]);
    dst[3] = make_float4(h[12], h[13], h[14], h[15]);
}

__device__ __forceinline__ void acc4(float4& a, const float4 b) {
    a.x += b.x; a.y += b.y; a.z += b.z; a.w += b.w;
}

// 6) layer1 gather + epilogue + layer2 linear:
//    t = hs1[i] + sum_nbr hs1[src];  v = relu(dinv*t + b1);  hs2 = (v@W2)*dinv
__global__ void k_layer1(const float* __restrict__ b1, const float* __restrict__ W2) {
    __shared__ float sW[256];
    __shared__ float sb[16];
    if (threadIdx.x < 256) sW[threadIdx.x] = W2[threadIdx.x];
    if (threadIdx.x < 16)  sb[threadIdx.x] = b1[threadIdx.x];
    __syncthreads();
    int i = blockIdx.x * blockDim.x + threadIdx.x;
    if (i >= NN) return;
    const float4* hs = g_hs1;
    float4 a0 = __ldg(hs + i * 4 + 0);
    float4 a1 = __ldg(hs + i * 4 + 1);
    float4 a2 = __ldg(hs + i * 4 + 2);
    float4 a3 = __ldg(hs + i * 4 + 3);
    int s  = g_start[i];
    int e2 = g_start[i + 1];
#pragma unroll 4
    for (int e = s; e < e2; e++) {
        int r = __ldg(&g_srcs[e]) * 4;
        acc4(a0, __ldg(hs + r + 0));
        acc4(a1, __ldg(hs + r + 1));
        acc4(a2, __ldg(hs + r + 2));
        acc4(a3, __ldg(hs + r + 3));
    }
    float di = g_dinv[i];
    float v[16];
    v[0]  = fmaxf(fmaf(di, a0.x, sb[0]),  0.f);
    v[1]  = fmaxf(fmaf(di, a0.y, sb[1]),  0.f);
    v[2]  = fmaxf(fmaf(di, a0.z, sb[2]),  0.f);
    v[3]  = fmaxf(fmaf(di, a0.w, sb[3]),  0.f);
    v[4]  = fmaxf(fmaf(di, a1.x, sb[4]),  0.f);
    v[5]  = fmaxf(fmaf(di, a1.y, sb[5]),  0.f);
    v[6]  = fmaxf(fmaf(di, a1.z, sb[6]),  0.f);
    v[7]  = fmaxf(fmaf(di, a1.w, sb[7]),  0.f);
    v[8]  = fmaxf(fmaf(di, a2.x, sb[8]),  0.f);
    v[9]  = fmaxf(fmaf(di, a2.y, sb[9]),  0.f);
    v[10] = fmaxf(fmaf(di, a2.z, sb[10]), 0.f);
    v[11] = fmaxf(fmaf(di, a2.w, sb[11]), 0.f);
    v[12] = fmaxf(fmaf(di, a3.x, sb[12]), 0.f);
    v[13] = fmaxf(fmaf(di, a3.y, sb[13]), 0.f);
    v[14] = fmaxf(fmaf(di, a3.z, sb[14]), 0.f);
    v[15] = fmaxf(fmaf(di, a3.w, sb[15]), 0.f);
    float o[16];
#pragma unroll
    for (int j = 0; j < 16; j++) {
        float acc = 0.f;
#pragma unroll
        for (int k = 0; k < 16; k++)
            acc = fmaf(v[k], sW[k * 16 + j], acc);
        o[j] = di * acc;
    }
    float4* dst = &g_hs2[i * 4];
    dst[0] = make_float4(o[0],  o[1],  o[2],  o[3]);
    dst[1] = make_float4(o[4],  o[5],  o[6],  o[7]);
    dst[2] = make_float4(o[8],  o[9],  o[10], o[11]);
    dst[3] = make_float4(o[12], o[13], o[14], o[15]);
}

// 7) layer2 gather + epilogue + pool:
//    t = hs2[i] + sum_nbr hs2[src];  h2 = dinv*t + b2;  pool[batch[i]] += h2
__global__ void k_layer2(const float* __restrict__ b2) {
    __shared__ float sb[16];
    if (threadIdx.x < 16) sb[threadIdx.x] = b2[threadIdx.x];
    __syncthreads();
    int i = blockIdx.x * blockDim.x + threadIdx.x;
    if (i >= NN) return;
    const float4* hs = g_hs2;
    float4 a0 = __ldg(hs + i * 4 + 0);
    float4 a1 = __ldg(hs + i * 4 + 1);
    float4 a2 = __ldg(hs + i * 4 + 2);
    float4 a3 = __ldg(hs + i * 4 + 3);
    int s  = g_start[i];
    int e2 = g_start[i + 1];
#pragma unroll 4
    for (int e = s; e < e2; e++) {
        int r = __ldg(&g_srcs[e]) * 4;
        acc4(a0, __ldg(hs + r + 0));
        acc4(a1, __ldg(hs + r + 1));
        acc4(a2, __ldg(hs + r + 2));
        acc4(a3, __ldg(hs + r + 3));
    }
    float di = g_dinv[i];
    int g = g_batch32[i];
    float* dst = (float*)&g_pool[g * 4];
    float4 r0 = make_float4(fmaf(di, a0.x, sb[0]),  fmaf(di, a0.y, sb[1]),
                            fmaf(di, a0.z, sb[2]),  fmaf(di, a0.w, sb[3]));
    float4 r1 = make_float4(fmaf(di, a1.x, sb[4]),  fmaf(di, a1.y, sb[5]),
                            fmaf(di, a1.z, sb[6]),  fmaf(di, a1.w, sb[7]));
    float4 r2 = make_float4(fmaf(di, a2.x, sb[8]),  fmaf(di, a2.y, sb[9]),
                            fmaf(di, a2.z, sb[10]), fmaf(di, a2.w, sb[11]));
    float4 r3 = make_float4(fmaf(di, a3.x, sb[12]), fmaf(di, a3.y, sb[13]),
                            fmaf(di, a3.z, sb[14]), fmaf(di, a3.w, sb[15]));
    red_add_v4(dst + 0,  r0);
    red_add_v4(dst + 4,  r1);
    red_add_v4(dst + 8,  r2);
    red_add_v4(dst + 12, r3);
}

// 8) per-graph head: logits = pool @ Wlin + blin; log_softmax
__global__ void k_logits(const float* __restrict__ Wlin, const float* __restrict__ blin,
                         float* __restrict__ out) {
    int g = blockIdx.x * blockDim.x + threadIdx.x;
    if (g >= NG) return;
    float gv[16];
#pragma unroll
    for (int q = 0; q < 4; q++) {
        float4 p = g_pool[g * 4 + q];
        gv[q * 4 + 0] = p.x; gv[q * 4 + 1] = p.y;
        gv[q * 4 + 2] = p.z; gv[q * 4 + 3] = p.w;
    }
    float lg[7];
#pragma unroll
    for (int o = 0; o < 7; o++) {
        float acc = __ldg(blin + o);
#pragma unroll
        for (int k = 0; k < 16; k++)
            acc = fmaf(gv[k], __ldg(Wlin + k * 7 + o), acc);
        lg[o] = acc;
    }
    float m = lg[0];
#pragma unroll
    for (int o = 1; o < 7; o++) m = fmaxf(m, lg[o]);
    float s = 0.f;
#pragma unroll
    for (int o = 0; o < 7; o++) s += expf(lg[o] - m);
    float ls = logf(s) + m;
#pragma unroll
    for (int o = 0; o < 7; o++) out[g * 7 + o] = lg[o] - ls;
}

// ---------------------------------------------------------------------------
extern "C" void kernel_launch(void* const* d_in, const int* in_sizes, int n_in,
                              void* d_out, int out_size) {
    int p = 0;
    const float* x     = (const float*)d_in[p]; p++;
    const void*  ei    = d_in[p];
    int twoE = in_sizes[p];
    int E = twoE / 2; p++;
    const void*  batch = d_in[p]; p++;
    if (p < n_in && in_sizes[p] == 1) p++;  // skip scalar num_graphs if present
    const float* W1   = (const float*)d_in[p]; p++;
    const float* b1   = (const float*)d_in[p]; p++;
    const float* W2   = (const float*)d_in[p]; p++;
    const float* b2   = (const float*)d_in[p]; p++;
    const float* Wlin = (const float*)d_in[p]; p++;
    const float* blin = (const float*)d_in[p]; p++;
    float* out = (float*)d_out;

    const int TB = 256;
    int gN  = (NN + TB - 1) / TB;
    int gE  = (E + TB - 1) / TB;
    int g2E = (twoE + TB - 1) / TB;
    int gP  = (NG * 4 + TB - 1) / TB > gN ? (NG * 4 + TB - 1) / TB : gN;

    k_detect    <<<1,    TB>>>(ei, twoE);
    k_init      <<<gP,   TB>>>();
    k_conv_edges<<<g2E,  TB>>>(ei, twoE);
    k_conv_batch<<<gN,   TB>>>(batch);
    k_scanA     <<<NBLK, TB>>>();
    k_scanB     <<<1,    32>>>();
    k_scanC     <<<NBLK, TB>>>();
    k_bucket    <<<gE,   TB>>>(E);
    k_hs1       <<<gN,   TB>>>(x, W1);
    k_layer1    <<<gN,   TB>>>(b1, W2);
    k_layer2    <<<gN,   TB>>>(b2);
    k_logits    <<<(NG + TB - 1) / TB, TB>>>(Wlin, blin, out);
}

// round 5
// speedup vs baseline: 1.7199x; 1.4961x over previous
#include <cuda_runtime.h>

// GCN: h1 = relu(GCNConv(x, W1, b1)); h2 = GCNConv(h1, W2, b2);
// g = segment_sum(h2, batch); out = log_softmax(g @ Wlin + blin)
//
// out[c] = dinv[c] * ( sum_{e: col=c} hs[row] + hs[c] ) + b,  hs = (x@W)*dinv.
// CSR built on device each launch; gather uses 4 lanes per node (one float4
// quarter each) for full occupancy + coalesced 64B per edge.

static const int NN = 100000;
static const int NG = 1024;
static const int EMAX = 3200000;
static const int NBLK = (NN + 255) / 256;   // 391 scan blocks

// Scratch (device globals; no allocation allowed)
__device__ int    g_is64;
__device__ int    g_idx32[2 * EMAX];   // [0,E): rows, [E,2E): cols
__device__ int    g_batch32[NN];
__device__ int    g_degi[NN];
__device__ int    g_start[NN + 1];
__device__ int    g_cursor[NN];
__device__ int    g_bsum[NBLK];
__device__ int    g_boff[NBLK];
__device__ int    g_srcs[EMAX];
__device__ __align__(16) float g_dinv[NN];
__device__ float4 g_hs1[NN * 4];
__device__ float4 g_hs2[NN * 4];
__device__ float4 g_pool[NG * 4];

__device__ __forceinline__ void red_add_v4(float* addr, float4 v) {
    asm volatile("red.global.add.v4.f32 [%0], {%1, %2, %3, %4};"
                 :: "l"(addr), "f"(v.x), "f"(v.y), "f"(v.z), "f"(v.w)
                 : "memory");
}

// ---------------------------------------------------------------------------
// 1) init (zero deg + pool) with dtype-detect fused into block 0
__global__ void k_init(const void* __restrict__ ei, int twoE) {
    int i = blockIdx.x * blockDim.x + threadIdx.x;
    if (i < NN) g_degi[i] = 0;
    if (i < NG * 4) g_pool[i] = make_float4(0.f, 0.f, 0.f, 0.f);
    if (blockIdx.x == 0) {
        __shared__ int bad;
        if (threadIdx.x == 0) bad = 0;
        __syncthreads();
        const long long* p64 = (const long long*)ei;
        int n = twoE / 2 < 2048 ? twoE / 2 : 2048;
        for (int k = threadIdx.x; k < n; k += blockDim.x) {
            unsigned long long v = (unsigned long long)p64[k];
            if (v >> 32) bad = 1;   // benign race
        }
        __syncthreads();
        if (threadIdx.x == 0) g_is64 = bad ? 0 : 1;
    }
}

// 2) convert edges (+ fused degree count) and batch to int32 scratch
__global__ void k_conv(const void* __restrict__ ei, const void* __restrict__ batch,
                       int twoE) {
    int i = blockIdx.x * blockDim.x + threadIdx.x;
    int E = twoE >> 1;
    int is64 = g_is64;
    if (i < twoE) {
        int v = is64 ? (int)((const long long*)ei)[i] : ((const int*)ei)[i];
        g_idx32[i] = v;
        if (i >= E) atomicAdd(&g_degi[v], 1);   // cols half
    }
    if (i < NN) {
        g_batch32[i] = is64 ? (int)((const long long*)batch)[i]
                            : ((const int*)batch)[i];
    }
}

// 3) prefix scan of degrees -> CSR starts
__global__ void k_scanA() {
    __shared__ int sh[256];
    int t = threadIdx.x;
    int i = blockIdx.x * 256 + t;
    sh[t] = (i < NN) ? g_degi[i] : 0;
    __syncthreads();
    for (int off = 128; off > 0; off >>= 1) {
        if (t < off) sh[t] += sh[t + off];
        __syncthreads();
    }
    if (t == 0) g_bsum[blockIdx.x] = sh[0];
}

__global__ void k_scanB() {
    __shared__ int sh[512];
    int t = threadIdx.x;
    int v = (t < NBLK) ? g_bsum[t] : 0;
    sh[t] = v;
    __syncthreads();
    for (int off = 1; off < 512; off <<= 1) {
        int a = (t >= off) ? sh[t - off] : 0;
        __syncthreads();
        sh[t] += a;
        __syncthreads();
    }
    if (t < NBLK) g_boff[t] = sh[t] - v;
    if (t == NBLK - 1) g_start[NN] = sh[t];
}

__global__ void k_scanC() {
    __shared__ int sh[256];
    int t = threadIdx.x;
    int i = blockIdx.x * 256 + t;
    int v = (i < NN) ? g_degi[i] : 0;
    sh[t] = v;
    __syncthreads();
    for (int off = 1; off < 256; off <<= 1) {
        int add = (t >= off) ? sh[t - off] : 0;
        __syncthreads();
        sh[t] += add;
        __syncthreads();
    }
    if (i < NN) {
        int excl = g_boff[blockIdx.x] + sh[t] - v;
        g_start[i]  = excl;
        g_cursor[i] = excl;
        g_dinv[i]   = rsqrtf((float)(v + 1));   // +1 self loop
    }
}

// 4) bucket edge sources by target -> g_srcs
__global__ void k_bucket(int E) {
    int e = blockIdx.x * blockDim.x + threadIdx.x;
    if (e >= E) return;
    int r = g_idx32[e];
    int c = g_idx32[E + e];
    int pos = atomicAdd(&g_cursor[c], 1);
    g_srcs[pos] = r;
}

// 5) hs1 = (x @ W1) * dinv    (x: [N,3], W1: [3,16])
__global__ void k_hs1(const float* __restrict__ x, const float* __restrict__ W1) {
    __shared__ float sW[48];
    if (threadIdx.x < 48) sW[threadIdx.x] = W1[threadIdx.x];
    __syncthreads();
    int i = blockIdx.x * blockDim.x + threadIdx.x;
    if (i >= NN) return;
    float x0 = __ldg(x + 3 * i + 0);
    float x1 = __ldg(x + 3 * i + 1);
    float x2 = __ldg(x + 3 * i + 2);
    float di = g_dinv[i];
    float h[16];
#pragma unroll
    for (int j = 0; j < 16; j++)
        h[j] = di * (x0 * sW[j] + x1 * sW[16 + j] + x2 * sW[32 + j]);
    float4* dst = &g_hs1[i * 4];
    dst[0] = make_float4(h[0],  h[1],  h[2],  h[3]);
    dst[1] = make_float4(h[4],  h[5],  h[6],  h[7]);
    dst[2] = make_float4(h[8],  h[9],  h[10], h[11]);
    dst[3] = make_float4(h[12], h[13], h[14], h[15]);
}

__device__ __forceinline__ void acc4(float4& a, const float4 b) {
    a.x += b.x; a.y += b.y; a.z += b.z; a.w += b.w;
}

// 6) layer1: 4 lanes per node gather + relu + 16x16 matmul via warp shuffles
__global__ void k_layer1(const float* __restrict__ b1, const float* __restrict__ W2) {
    __shared__ float sW[256];
    __shared__ float sb[16];
    if (threadIdx.x < 256) sW[threadIdx.x] = W2[threadIdx.x];
    if (threadIdx.x < 16)  sb[threadIdx.x] = b1[threadIdx.x];
    __syncthreads();
    int t = blockIdx.x * blockDim.x + threadIdx.x;
    int node = t >> 2;
    int q = t & 3;
    if (node >= NN) return;
    const float4* hs = g_hs1;
    float4 acc = __ldg(hs + node * 4 + q);
    int s  = g_start[node];
    int e2 = g_start[node + 1];
#pragma unroll 4
    for (int e = s; e < e2; e++) {
        int r = __ldg(&g_srcs[e]);
        acc4(acc, __ldg(hs + r * 4 + q));
    }
    float di = g_dinv[node];
    float4 myv;
    myv.x = fmaxf(fmaf(di, acc.x, sb[q * 4 + 0]), 0.f);
    myv.y = fmaxf(fmaf(di, acc.y, sb[q * 4 + 1]), 0.f);
    myv.z = fmaxf(fmaf(di, acc.z, sb[q * 4 + 2]), 0.f);
    myv.w = fmaxf(fmaf(di, acc.w, sb[q * 4 + 3]), 0.f);
    // matmul: thread q computes outputs j in [4q, 4q+4)
    int lane = threadIdx.x & 31;
    int base = lane & ~3;
    float o0 = 0.f, o1 = 0.f, o2 = 0.f, o3 = 0.f;
#pragma unroll
    for (int p = 0; p < 4; p++) {
        float4 vp;
        vp.x = __shfl_sync(0xffffffff, myv.x, base + p);
        vp.y = __shfl_sync(0xffffffff, myv.y, base + p);
        vp.z = __shfl_sync(0xffffffff, myv.z, base + p);
        vp.w = __shfl_sync(0xffffffff, myv.w, base + p);
        const float* w0 = &sW[(p * 4 + 0) * 16 + q * 4];
        const float* w1 = &sW[(p * 4 + 1) * 16 + q * 4];
        const float* w2 = &sW[(p * 4 + 2) * 16 + q * 4];
        const float* w3 = &sW[(p * 4 + 3) * 16 + q * 4];
        o0 = fmaf(vp.x, w0[0], fmaf(vp.y, w1[0], fmaf(vp.z, w2[0], fmaf(vp.w, w3[0], o0))));
        o1 = fmaf(vp.x, w0[1], fmaf(vp.y, w1[1], fmaf(vp.z, w2[1], fmaf(vp.w, w3[1], o1))));
        o2 = fmaf(vp.x, w0[2], fmaf(vp.y, w1[2], fmaf(vp.z, w2[2], fmaf(vp.w, w3[2], o2))));
        o3 = fmaf(vp.x, w0[3], fmaf(vp.y, w1[3], fmaf(vp.z, w2[3], fmaf(vp.w, w3[3], o3))));
    }
    g_hs2[node * 4 + q] = make_float4(di * o0, di * o1, di * o2, di * o3);
}

// 7) layer2: 4 lanes per node gather + bias + pool reduction
__global__ void k_layer2(const float* __restrict__ b2) {
    __shared__ float sb[16];
    if (threadIdx.x < 16) sb[threadIdx.x] = b2[threadIdx.x];
    __syncthreads();
    int t = blockIdx.x * blockDim.x + threadIdx.x;
    int node = t >> 2;
    int q = t & 3;
    if (node >= NN) return;
    const float4* hs = g_hs2;
    float4 acc = __ldg(hs + node * 4 + q);
    int s  = g_start[node];
    int e2 = g_start[node + 1];
#pragma unroll 4
    for (int e = s; e < e2; e++) {
        int r = __ldg(&g_srcs[e]);
        acc4(acc, __ldg(hs + r * 4 + q));
    }
    float di = g_dinv[node];
    int g = g_batch32[node];
    float4 r;
    r.x = fmaf(di, acc.x, sb[q * 4 + 0]);
    r.y = fmaf(di, acc.y, sb[q * 4 + 1]);
    r.z = fmaf(di, acc.z, sb[q * 4 + 2]);
    r.w = fmaf(di, acc.w, sb[q * 4 + 3]);
    red_add_v4((float*)&g_pool[g * 4 + q], r);
}

// 8) per-graph head: logits = pool @ Wlin + blin; log_softmax
__global__ void k_logits(const float* __restrict__ Wlin, const float* __restrict__ blin,
                         float* __restrict__ out) {
    int g = blockIdx.x * blockDim.x + threadIdx.x;
    if (g >= NG) return;
    float gv[16];
#pragma unroll
    for (int q = 0; q < 4; q++) {
        float4 p = g_pool[g * 4 + q];
        gv[q * 4 + 0] = p.x; gv[q * 4 + 1] = p.y;
        gv[q * 4 + 2] = p.z; gv[q * 4 + 3] = p.w;
    }
    float lg[7];
#pragma unroll
    for (int o = 0; o < 7; o++) {
        float acc = __ldg(blin + o);
#pragma unroll
        for (int k = 0; k < 16; k++)
            acc = fmaf(gv[k], __ldg(Wlin + k * 7 + o), acc);
        lg[o] = acc;
    }
    float m = lg[0];
#pragma unroll
    for (int o = 1; o < 7; o++) m = fmaxf(m, lg[o]);
    float s = 0.f;
#pragma unroll
    for (int o = 0; o < 7; o++) s += expf(lg[o] - m);
    float ls = logf(s) + m;
#pragma unroll
    for (int o = 0; o < 7; o++) out[g * 7 + o] = lg[o] - ls;
}

// ---------------------------------------------------------------------------
extern "C" void kernel_launch(void* const* d_in, const int* in_sizes, int n_in,
                              void* d_out, int out_size) {
    int p = 0;
    const float* x     = (const float*)d_in[p]; p++;
    const void*  ei    = d_in[p];
    int twoE = in_sizes[p];
    int E = twoE / 2; p++;
    const void*  batch = d_in[p]; p++;
    if (p < n_in && in_sizes[p] == 1) p++;  // skip scalar num_graphs if present
    const float* W1   = (const float*)d_in[p]; p++;
    const float* b1   = (const float*)d_in[p]; p++;
    const float* W2   = (const float*)d_in[p]; p++;
    const float* b2   = (const float*)d_in[p]; p++;
    const float* Wlin = (const float*)d_in[p]; p++;
    const float* blin = (const float*)d_in[p]; p++;
    float* out = (float*)d_out;

    const int TB = 256;
    int gN   = (NN + TB - 1) / TB;
    int gN4  = (NN * 4 + TB - 1) / TB;
    int gE   = (E + TB - 1) / TB;
    int g2E  = (twoE + TB - 1) / TB;
    int gIni = (NG * 4 + TB - 1) / TB > gN ? (NG * 4 + TB - 1) / TB : gN;

    k_init   <<<gIni, TB>>>(ei, twoE);
    k_conv   <<<g2E,  TB>>>(ei, batch, twoE);
    k_scanA  <<<NBLK, TB>>>();
    k_scanB  <<<1,    512>>>();
    k_scanC  <<<NBLK, TB>>>();
    k_bucket <<<gE,   TB>>>(E);
    k_hs1    <<<gN,   TB>>>(x, W1);
    k_layer1 <<<gN4,  TB>>>(b1, W2);
    k_layer2 <<<gN4,  TB>>>(b2);
    k_logits <<<(NG + TB - 1) / TB, TB>>>(Wlin, blin, out);
}